// round 5
// baseline (speedup 1.0000x reference)
#include <cuda_runtime.h>
#include <cuda_bf16.h>
#include <cstdint>

#define HHn 8
#define LLn 128
#define DDn 512
#define DIn 2048
#define NBS 128
#define NROW 1024

typedef unsigned long long u64;

// ---------------- scratch (device globals; no allocation allowed) ----------
__device__ float g_t  [NROW*DDn];
__device__ float g_o  [NROW*DDn];
__device__ float g_logits[NROW*LLn];
__device__ __nv_bfloat16 g_axh[NROW*DDn];
__device__ __nv_bfloat16 g_axl[NROW*DDn];
__device__ __nv_bfloat16 g_oh [NROW*DDn];
__device__ __nv_bfloat16 g_ol [NROW*DDn];
__device__ __nv_bfloat16 g_hh [NROW*DIn];
__device__ __nv_bfloat16 g_hl [NROW*DIn];
__device__ __nv_bfloat16 g_vwh[DDn*DDn];
__device__ __nv_bfloat16 g_vwl[DDn*DDn];
__device__ __nv_bfloat16 g_w1h[DIn*DDn];
__device__ __nv_bfloat16 g_w1l[DIn*DDn];
__device__ __nv_bfloat16 g_w2h[DDn*DIn];
__device__ __nv_bfloat16 g_w2l[DDn*DIn];

// ---------------- helpers ---------------------------------------------------
__device__ __forceinline__ uint32_t smem_u32(const void* p) {
    uint32_t a;
    asm("{ .reg .u64 t; cvta.to.shared.u64 t, %1; cvt.u32.u64 %0, t; }"
        : "=r"(a) : "l"(p));
    return a;
}
__device__ __forceinline__ void bsplit(float v, __nv_bfloat16& h, __nv_bfloat16& l) {
    h = __float2bfloat16(v);
    l = __float2bfloat16(v - __bfloat162float(h));
}
__device__ __forceinline__ void fma2(u64 &d, u64 a, u64 b) {
    asm("fma.rn.f32x2 %0, %1, %2, %0;" : "+l"(d) : "l"(a), "l"(b));
}
__device__ __forceinline__ u64 pk2(float a, float b) {
    u64 r; asm("mov.b64 %0, {%1,%2};" : "=l"(r) : "f"(a), "f"(b)); return r;
}
__device__ __forceinline__ float2 upk2(u64 v) {
    float2 r; asm("mov.b64 {%0,%1}, %2;" : "=f"(r.x), "=f"(r.y) : "l"(v)); return r;
}

#define CPA16(dst, src) \
    asm volatile("cp.async.cg.shared.global [%0], [%1], 16;" \
                 :: "r"(dst), "l"(src) : "memory")
#define CPA_COMMIT() asm volatile("cp.async.commit_group;" ::: "memory")
#define CPA_WAIT0()  asm volatile("cp.async.wait_group 0;" ::: "memory")

#define LDSM4(r, addr) \
    asm volatile("ldmatrix.sync.aligned.m8n8.x4.shared.b16 {%0,%1,%2,%3}, [%4];" \
                 : "=r"((r)[0]), "=r"((r)[1]), "=r"((r)[2]), "=r"((r)[3]) \
                 : "r"(addr))

#define MMA_BF16(c, a, b) \
    asm volatile("mma.sync.aligned.m16n8k16.row.col.f32.bf16.bf16.f32 " \
        "{%0,%1,%2,%3}, {%4,%5,%6,%7}, {%8,%9}, {%0,%1,%2,%3};" \
        : "+f"((c)[0]), "+f"((c)[1]), "+f"((c)[2]), "+f"((c)[3]) \
        : "r"((a)[0]), "r"((a)[1]), "r"((a)[2]), "r"((a)[3]), \
          "r"((b)[0]), "r"((b)[1]))

__device__ __forceinline__ uint32_t tile_off(int row, int chunk) {
    return (uint32_t)(row * 64 + ((chunk ^ ((row >> 1) & 3)) << 4));
}

// ---------------------------------------------------------------------------
// K1: logits[bs][h][l] = sum_d x[bs,l,d] * w[h,l,d].
// grid (l=128, half=2); CTA covers 64 bs values for one l.
// ---------------------------------------------------------------------------
__global__ __launch_bounds__(256) void logits_kernel(
    const float* __restrict__ x, const float* __restrict__ w,
    float* __restrict__ logits)
{
    __shared__ __align__(16) float w_s[HHn][DDn];
    const int l = blockIdx.x, half = blockIdx.y;
    const int tid = threadIdx.x, warp = tid >> 5, lane = tid & 31;

    #pragma unroll
    for (int i = 0; i < 4; i++) {
        int idx = tid + i * 256;          // float4 units, 1024 total
        int h = idx >> 7, d4 = idx & 127;
        ((float4*)w_s[h])[d4] =
            ((const float4*)(w + ((size_t)(h * LLn + l)) * DDn))[d4];
    }
    __syncthreads();

    const int j  = __brev((unsigned)lane) >> 27;   // value index this lane owns
    const int jb = j >> 3, jh = j & 7;

    #pragma unroll
    for (int q = 0; q < 2; q++) {
        const int bs0 = half * 64 + warp * 8 + q * 4;
        u64 acc[4][HHn];
        #pragma unroll
        for (int b = 0; b < 4; b++)
            #pragma unroll
            for (int h = 0; h < HHn; h++) acc[b][h] = 0ull;

        #pragma unroll
        for (int c = 0; c < 4; c++) {
            const int d4 = c * 32 + lane;          // double2 index within 512 floats
            u64 xp[4][2];
            #pragma unroll
            for (int b = 0; b < 4; b++) {
                double2 xv = ((const double2*)
                    (x + ((size_t)((bs0 + b) * LLn + l)) * DDn))[d4];
                xp[b][0] = __double_as_longlong(xv.x);
                xp[b][1] = __double_as_longlong(xv.y);
            }
            #pragma unroll
            for (int h = 0; h < HHn; h++) {
                double2 wv = ((const double2*)w_s[h])[d4];
                u64 w0 = __double_as_longlong(wv.x);
                u64 w1 = __double_as_longlong(wv.y);
                #pragma unroll
                for (int b = 0; b < 4; b++) {
                    fma2(acc[b][h], xp[b][0], w0);
                    fma2(acc[b][h], xp[b][1], w1);
                }
            }
        }
        float vals[32];
        #pragma unroll
        for (int b = 0; b < 4; b++)
            #pragma unroll
            for (int h = 0; h < HHn; h++) {
                float2 p = upk2(acc[b][h]);
                vals[b * 8 + h] = p.x + p.y;
            }
        // multi-value butterfly: 31 shfl; lane ends owning vals index bitrev5(lane)
        #pragma unroll
        for (int s = 0; s < 5; s++) {
            const int n = 32 >> s;
            const int off = 1 << s;
            const bool up = (lane & off) != 0;
            #pragma unroll
            for (int i = 0; i < (n >> 1); i++) {
                float kept = up ? vals[i + (n >> 1)] : vals[i];
                float sent = up ? vals[i] : vals[i + (n >> 1)];
                float r = __shfl_xor_sync(0xffffffffu, sent, off);
                vals[i] = kept + r;
            }
        }
        logits[((size_t)(bs0 + jb) * HHn + jh) * LLn + l] = vals[0];
    }
}

// ---------------------------------------------------------------------------
// K2: fused softmax + ax. grid (bs=128, dhalf=2), block 256.
// ax[bs,h,d] = sum_l softmax(logits)[bs,h,l] * x[bs,l,d], split bf16.
// ---------------------------------------------------------------------------
__global__ __launch_bounds__(256) void ax_kernel(
    const float* __restrict__ x, const float* __restrict__ logits,
    const int* __restrict__ mask, float* __restrict__ attn_out,
    __nv_bfloat16* __restrict__ axh, __nv_bfloat16* __restrict__ axl)
{
    __shared__ float  a_s[HHn][LLn];          // softmax result
    __shared__ __align__(8) float2 ap[LLn][HHn/2];  // packed (2p,2p+1) pairs per l
    const int bs = blockIdx.x, dh = blockIdx.y;
    const int tid = threadIdx.x, warp = tid >> 5, lane = tid & 31;

    // ---- softmax: warp per head ----
    {
        const int h = warp;
        const int row = bs * HHn + h;
        const float invT = 0.0441941738241592f;  // 1/sqrt(512)
        float v[4], mx = -3.4e38f;
        #pragma unroll
        for (int i = 0; i < 4; i++) {
            int l = lane + 32 * i;
            float lg = logits[(size_t)row * LLn + l] * invT;
            if (mask[bs * LLn + l] == 0) lg = -1e9f;
            v[i] = lg; mx = fmaxf(mx, lg);
        }
        #pragma unroll
        for (int off = 16; off; off >>= 1)
            mx = fmaxf(mx, __shfl_xor_sync(0xffffffffu, mx, off));
        float sum = 0.f;
        #pragma unroll
        for (int i = 0; i < 4; i++) { v[i] = __expf(v[i] - mx); sum += v[i]; }
        #pragma unroll
        for (int off = 16; off; off >>= 1)
            sum += __shfl_xor_sync(0xffffffffu, sum, off);
        float inv = 1.f / sum;
        #pragma unroll
        for (int i = 0; i < 4; i++) {
            int l = lane + 32 * i;
            float a = v[i] * inv;
            a_s[h][l] = a;
            if (dh == 0 && attn_out) attn_out[(size_t)row * LLn + l] = a;
        }
    }
    __syncthreads();

    // ---- pack h-pairs for f32x2 ----
    #pragma unroll
    for (int i = tid; i < LLn * 4; i += 256) {
        int l = i >> 2, p = i & 3;
        ap[l][p] = make_float2(a_s[2 * p][l], a_s[2 * p + 1][l]);
    }
    __syncthreads();

    // ---- ax: one d-column per thread ----
    const int d = dh * 256 + tid;
    const float* xp = x + (size_t)bs * LLn * DDn + d;

    u64 acc[4];
    #pragma unroll
    for (int p = 0; p < 4; p++) acc[p] = 0ull;

    #pragma unroll 4
    for (int l = 0; l < LLn; l++) {
        float xv = xp[(size_t)l * DDn];
        u64 xx = pk2(xv, xv);
        #pragma unroll
        for (int p = 0; p < 4; p++) {
            u64 av = __double_as_longlong(*(const double*)&ap[l][p]);
            fma2(acc[p], av, xx);
        }
    }
    #pragma unroll
    for (int p = 0; p < 4; p++) {
        float2 s = upk2(acc[p]);
        size_t o0 = ((size_t)bs * HHn + 2 * p) * DDn + d;
        size_t o1 = ((size_t)bs * HHn + 2 * p + 1) * DDn + d;
        __nv_bfloat16 bh, bl;
        bsplit(s.x, bh, bl); axh[o0] = bh; axl[o0] = bl;
        bsplit(s.y, bh, bl); axh[o1] = bh; axl[o1] = bl;
    }
}

// ---------------------------------------------------------------------------
// HMMA split-bf16 GEMM: C[M,N] = A[M,K] @ B[N,K]^T (+bias,+relu,+res)
// ---------------------------------------------------------------------------
template<int BM, int WM, int WN, bool RELU, bool RES, bool OSPLIT>
__global__ __launch_bounds__(WM*WN*32, 1) void gemm_mma(
    const __nv_bfloat16* __restrict__ Ah, const __nv_bfloat16* __restrict__ Al,
    const __nv_bfloat16* __restrict__ Bh, const __nv_bfloat16* __restrict__ Bl,
    const float* __restrict__ bias, const float* __restrict__ res,
    float* __restrict__ C, __nv_bfloat16* __restrict__ Ch,
    __nv_bfloat16* __restrict__ Cl, int M, int N, int K)
{
    constexpr int BN = BM, BK = 32;
    constexpr int THREADS = WM * WN * 32;
    constexpr int ARR_BYTES = BM * 64;
    constexpr int STAGE = 4 * ARR_BYTES;
    constexpr int MT = (BM / WM) / 16;
    constexpr int NT = (BN / WN) / 8;
    constexpr int CHUNKS = 4 * BM * 4;
    constexpr int CPT = CHUNKS / THREADS;

    extern __shared__ __align__(128) char dsm[];
    const uint32_t sb = smem_u32(dsm);

    const int tid = threadIdx.x, wid = tid >> 5, lane = tid & 31;
    const int bm = blockIdx.y * BM, bn = blockIdx.x * BN;
    const int wm = wid / WN, wn = wid % WN;
    const int KT = K / BK;

    auto load_stage = [&](int kt, int s) {
        const uint32_t base = sb + s * STAGE;
        #pragma unroll
        for (int i = 0; i < CPT; i++) {
            int id = tid + i * THREADS;
            int aid = id / (BM * 4);
            int wthin = id % (BM * 4);
            int row = wthin >> 2;
            int ck = wthin & 3;
            const __nv_bfloat16* g;
            if (aid == 0) g = Ah; else if (aid == 1) g = Al;
            else if (aid == 2) g = Bh; else g = Bl;
            int rowbase = (aid < 2) ? bm : bn;
            const __nv_bfloat16* src =
                g + (size_t)(rowbase + row) * K + (size_t)kt * BK + ck * 8;
            uint32_t dst = base + aid * ARR_BYTES + tile_off(row, ck);
            CPA16(dst, src);
        }
        CPA_COMMIT();
    };

    float c[MT][NT][4];
    #pragma unroll
    for (int i = 0; i < MT; i++)
        #pragma unroll
        for (int j = 0; j < NT; j++)
            #pragma unroll
            for (int q = 0; q < 4; q++) c[i][j][q] = 0.f;

    load_stage(0, 0);
    CPA_WAIT0();
    __syncthreads();

    const int aRow0 = wm * (BM / WM);
    const int bRow0 = wn * (BN / WN);

    for (int kt = 0; kt < KT; kt++) {
        if (kt + 1 < KT) load_stage(kt + 1, (kt + 1) & 1);

        const uint32_t base = sb + (kt & 1) * STAGE;
        const uint32_t sAh = base;
        const uint32_t sAl = base + ARR_BYTES;
        const uint32_t sBh = base + 2 * ARR_BYTES;
        const uint32_t sBl = base + 3 * ARR_BYTES;

        #pragma unroll
        for (int ks = 0; ks < 2; ks++) {
            uint32_t aH[MT][4], aL[MT][4];
            #pragma unroll
            for (int mt = 0; mt < MT; mt++) {
                int row = aRow0 + mt * 16 + (lane & 15);
                int ck = ks * 2 + (lane >> 4);
                uint32_t off = tile_off(row, ck);
                LDSM4(aH[mt], sAh + off);
                LDSM4(aL[mt], sAl + off);
            }
            uint32_t bH[NT][2], bL[NT][2];
            #pragma unroll
            for (int p = 0; p < NT / 2; p++) {
                int row = bRow0 + p * 16 + (lane & 7) + ((lane >> 4) << 3);
                int ck = ks * 2 + ((lane >> 3) & 1);
                uint32_t off = tile_off(row, ck);
                uint32_t r[4];
                LDSM4(r, sBh + off);
                bH[2*p][0] = r[0]; bH[2*p][1] = r[1];
                bH[2*p+1][0] = r[2]; bH[2*p+1][1] = r[3];
                LDSM4(r, sBl + off);
                bL[2*p][0] = r[0]; bL[2*p][1] = r[1];
                bL[2*p+1][0] = r[2]; bL[2*p+1][1] = r[3];
            }
            #pragma unroll
            for (int mt = 0; mt < MT; mt++)
                #pragma unroll
                for (int nt = 0; nt < NT; nt++) {
                    MMA_BF16(c[mt][nt], aH[mt], bH[nt]);
                    MMA_BF16(c[mt][nt], aH[mt], bL[nt]);
                    MMA_BF16(c[mt][nt], aL[mt], bH[nt]);
                }
        }
        CPA_WAIT0();
        __syncthreads();
    }

    #pragma unroll
    for (int mt = 0; mt < MT; mt++) {
        #pragma unroll
        for (int nt = 0; nt < NT; nt++) {
            int row = bm + aRow0 + mt * 16 + (lane >> 2);
            int col = bn + bRow0 + nt * 8 + ((lane & 3) << 1);
            #pragma unroll
            for (int half = 0; half < 2; half++) {
                int r = row + half * 8;
                float v0 = c[mt][nt][half * 2 + 0];
                float v1 = c[mt][nt][half * 2 + 1];
                if (bias) { v0 += bias[col]; v1 += bias[col + 1]; }
                if (RELU) { v0 = fmaxf(v0, 0.f); v1 = fmaxf(v1, 0.f); }
                if (RES) {
                    v0 += res[(size_t)r * N + col];
                    v1 += res[(size_t)r * N + col + 1];
                }
                if (OSPLIT) {
                    __nv_bfloat16 h, l;
                    bsplit(v0, h, l);
                    Ch[(size_t)r * N + col] = h; Cl[(size_t)r * N + col] = l;
                    bsplit(v1, h, l);
                    Ch[(size_t)r * N + col + 1] = h; Cl[(size_t)r * N + col + 1] = l;
                } else {
                    C[(size_t)r * N + col] = v0;
                    C[(size_t)r * N + col + 1] = v1;
                }
            }
        }
    }
}

// ---------------------------------------------------------------------------
// Fused split: all three weight tensors fp32 -> (bf16 hi, bf16 lo)
// ---------------------------------------------------------------------------
__global__ __launch_bounds__(256) void split3_kernel(
    const float4* __restrict__ vw, const float4* __restrict__ w1,
    const float4* __restrict__ w2,
    __nv_bfloat16* __restrict__ vwh, __nv_bfloat16* __restrict__ vwl,
    __nv_bfloat16* __restrict__ w1h, __nv_bfloat16* __restrict__ w1l,
    __nv_bfloat16* __restrict__ w2h, __nv_bfloat16* __restrict__ w2l)
{
    constexpr int N0 = DDn * DDn / 4;   // 65536
    constexpr int N1 = DIn * DDn / 4;   // 262144
    int i = blockIdx.x * blockDim.x + threadIdx.x;
    const float4* in; __nv_bfloat16 *hi, *lo; int k;
    if (i < N0)            { in = vw; hi = vwh; lo = vwl; k = i; }
    else if (i < N0 + N1)  { in = w1; hi = w1h; lo = w1l; k = i - N0; }
    else                   { in = w2; hi = w2h; lo = w2l; k = i - N0 - N1; }
    float4 v = in[k];
    __nv_bfloat16 h[4], l[4];
    bsplit(v.x, h[0], l[0]); bsplit(v.y, h[1], l[1]);
    bsplit(v.z, h[2], l[2]); bsplit(v.w, h[3], l[3]);
    *(ushort4*)(hi + 4 * (size_t)k) = make_ushort4(
        __bfloat16_as_ushort(h[0]), __bfloat16_as_ushort(h[1]),
        __bfloat16_as_ushort(h[2]), __bfloat16_as_ushort(h[3]));
    *(ushort4*)(lo + 4 * (size_t)k) = make_ushort4(
        __bfloat16_as_ushort(l[0]), __bfloat16_as_ushort(l[1]),
        __bfloat16_as_ushort(l[2]), __bfloat16_as_ushort(l[3]));
}

// ---------------------------------------------------------------------------
// LayerNorm D=512, one CTA/row; optional split bf16 outputs
// ---------------------------------------------------------------------------
__device__ __forceinline__ float block_sum(float v, float* red)
{
    const int lane = threadIdx.x & 31, warp = threadIdx.x >> 5;
    #pragma unroll
    for (int off = 16; off; off >>= 1)
        v += __shfl_xor_sync(0xffffffffu, v, off);
    if (lane == 0) red[warp] = v;
    __syncthreads();
    if (warp == 0) {
        float s = (lane < 8) ? red[lane] : 0.f;
        #pragma unroll
        for (int off = 4; off; off >>= 1)
            s += __shfl_xor_sync(0xffffffffu, s, off);
        if (lane == 0) red[0] = s;
    }
    __syncthreads();
    float rv = red[0];
    __syncthreads();
    return rv;
}

template<bool SPLIT>
__global__ __launch_bounds__(256) void ln_kernel(
    const float* __restrict__ in, const float* __restrict__ g,
    const float* __restrict__ b, float* __restrict__ out,
    __nv_bfloat16* __restrict__ oh, __nv_bfloat16* __restrict__ ol)
{
    __shared__ float red[8];
    const int row = blockIdx.x, tid = threadIdx.x;
    const float* r = in + (size_t)row * DDn;
    float v0 = r[tid], v1 = r[tid + 256];
    float mu = block_sum(v0 + v1, red) * (1.f / DDn);
    float e0 = v0 - mu, e1 = v1 - mu;
    float var = block_sum(e0 * e0 + e1 * e1, red) * (1.f / DDn);
    float inv = rsqrtf(var + 1e-6f);
    float y0 = e0 * inv * g[tid] + b[tid];
    float y1 = e1 * inv * g[tid + 256] + b[tid + 256];
    size_t i0 = (size_t)row * DDn + tid, i1 = i0 + 256;
    out[i0] = y0; out[i1] = y1;
    if (SPLIT) {
        __nv_bfloat16 h, l;
        bsplit(y0, h, l); oh[i0] = h; ol[i0] = l;
        bsplit(y1, h, l); oh[i1] = h; ol[i1] = l;
    }
}

// ---------------------------------------------------------------------------
extern "C" void kernel_launch(void* const* d_in, const int* in_sizes, int n_in,
                              void* d_out, int out_size)
{
    const float* x    = (const float*)d_in[0];
    const int*   mask = (const int*)  d_in[1];
    const float* w    = (const float*)d_in[2];
    const float* v_w  = (const float*)d_in[3];
    const float* ln_g = (const float*)d_in[4];
    const float* ln_b = (const float*)d_in[5];
    const float* w1   = (const float*)d_in[6];
    const float* b1   = (const float*)d_in[7];
    const float* w2   = (const float*)d_in[8];
    const float* b2   = (const float*)d_in[9];
    const float* fg   = (const float*)d_in[10];
    const float* fb   = (const float*)d_in[11];

    float *t, *o, *lg;
    __nv_bfloat16 *axh, *axl, *oh, *ol, *hh, *hl;
    __nv_bfloat16 *vwh, *vwl, *w1h, *w1l, *w2h, *w2l;
    cudaGetSymbolAddress((void**)&t,   g_t);
    cudaGetSymbolAddress((void**)&o,   g_o);
    cudaGetSymbolAddress((void**)&lg,  g_logits);
    cudaGetSymbolAddress((void**)&axh, g_axh);
    cudaGetSymbolAddress((void**)&axl, g_axl);
    cudaGetSymbolAddress((void**)&oh,  g_oh);
    cudaGetSymbolAddress((void**)&ol,  g_ol);
    cudaGetSymbolAddress((void**)&hh,  g_hh);
    cudaGetSymbolAddress((void**)&hl,  g_hl);
    cudaGetSymbolAddress((void**)&vwh, g_vwh);
    cudaGetSymbolAddress((void**)&vwl, g_vwl);
    cudaGetSymbolAddress((void**)&w1h, g_w1h);
    cudaGetSymbolAddress((void**)&w1l, g_w1l);
    cudaGetSymbolAddress((void**)&w2h, g_w2h);
    cudaGetSymbolAddress((void**)&w2l, g_w2l);

    float* y_out = (float*)d_out;
    float* attn_out = (out_size >= NROW * DDn + NROW * LLn)
                        ? (y_out + NROW * DDn) : nullptr;

    constexpr int SM128 = 2 * 4 * 128 * 64;  // 65536
    constexpr int SM64  = 2 * 4 * 64 * 64;   // 32768
    cudaFuncSetAttribute(gemm_mma<64, 2, 2, false, false, false>,
                         cudaFuncAttributeMaxDynamicSharedMemorySize, SM64);
    cudaFuncSetAttribute(gemm_mma<128, 2, 4, true, false, true>,
                         cudaFuncAttributeMaxDynamicSharedMemorySize, SM128);
    cudaFuncSetAttribute(gemm_mma<64, 2, 2, false, true, false>,
                         cudaFuncAttributeMaxDynamicSharedMemorySize, SM64);

    // all weight splits in one launch
    constexpr int NSPLIT = (DDn*DDn + DIn*DDn + DDn*DIn) / 4;  // 589824
    split3_kernel<<<NSPLIT/256, 256>>>(
        (const float4*)v_w, (const float4*)w1, (const float4*)w2,
        vwh, vwl, w1h, w1l, w2h, w2l);

    // attention: logits -> fused softmax + attn@x
    logits_kernel<<<dim3(LLn, 2), 256>>>(x, w, lg);
    ax_kernel<<<dim3(NBS, 2), 256>>>(x, lg, mask, attn_out, axh, axl);

    // t = ax @ v_w^T   (1024 x 512 x 512)
    gemm_mma<64, 2, 2, false, false, false>
        <<<dim3(DDn/64, NROW/64), 128, SM64>>>(
        axh, axl, vwh, vwl, nullptr, nullptr, t, nullptr, nullptr,
        NROW, DDn, DDn);

    // o = LN(t) (+ split)
    ln_kernel<true><<<NROW, 256>>>(t, ln_g, ln_b, o, oh, ol);

    // h = relu(o @ w1^T + b1)  (1024 x 2048 x 512)
    gemm_mma<128, 2, 4, true, false, true>
        <<<dim3(DIn/128, NROW/128), 256, SM128>>>(
        oh, ol, w1h, w1l, b1, nullptr, nullptr, hh, hl,
        NROW, DIn, DDn);

    // t = h @ w2^T + b2 + o  (1024 x 512 x 2048)
    gemm_mma<64, 2, 2, false, true, false>
        <<<dim3(DDn/64, NROW/64), 128, SM64>>>(
        hh, hl, w2h, w2l, b2, o, t, nullptr, nullptr,
        NROW, DDn, DIn);

    // y = LN(t)
    ln_kernel<false><<<NROW, 256>>>(t, fg, fb, y_out, nullptr, nullptr);
}

// round 6
// speedup vs baseline: 1.1569x; 1.1569x over previous
#include <cuda_runtime.h>
#include <cuda_bf16.h>
#include <cstdint>

#define HHn 8
#define LLn 128
#define DDn 512
#define DIn 2048
#define NBS 128
#define NROW 1024

typedef unsigned long long u64;

// ---------------- scratch (device globals; no allocation allowed) ----------
__device__ float g_o  [NROW*DDn];
__device__ float g_logits[NROW*LLn];
__device__ float g_p  [4][NROW*DDn];    // split-K partials (reused G0 then G2)
__device__ __nv_bfloat16 g_axh[NROW*DDn];
__device__ __nv_bfloat16 g_axl[NROW*DDn];
__device__ __nv_bfloat16 g_oh [NROW*DDn];
__device__ __nv_bfloat16 g_ol [NROW*DDn];
__device__ __nv_bfloat16 g_hh [NROW*DIn];
__device__ __nv_bfloat16 g_hl [NROW*DIn];
__device__ __nv_bfloat16 g_vwh[DDn*DDn];
__device__ __nv_bfloat16 g_vwl[DDn*DDn];
__device__ __nv_bfloat16 g_w1h[DIn*DDn];
__device__ __nv_bfloat16 g_w1l[DIn*DDn];
__device__ __nv_bfloat16 g_w2h[DDn*DIn];
__device__ __nv_bfloat16 g_w2l[DDn*DIn];

// ---------------- helpers ---------------------------------------------------
__device__ __forceinline__ uint32_t smem_u32(const void* p) {
    uint32_t a;
    asm("{ .reg .u64 t; cvta.to.shared.u64 t, %1; cvt.u32.u64 %0, t; }"
        : "=r"(a) : "l"(p));
    return a;
}
__device__ __forceinline__ void bsplit(float v, __nv_bfloat16& h, __nv_bfloat16& l) {
    h = __float2bfloat16(v);
    l = __float2bfloat16(v - __bfloat162float(h));
}
__device__ __forceinline__ void fma2(u64 &d, u64 a, u64 b) {
    asm("fma.rn.f32x2 %0, %1, %2, %0;" : "+l"(d) : "l"(a), "l"(b));
}
__device__ __forceinline__ u64 pk2(float a, float b) {
    u64 r; asm("mov.b64 %0, {%1,%2};" : "=l"(r) : "f"(a), "f"(b)); return r;
}
__device__ __forceinline__ float2 upk2(u64 v) {
    float2 r; asm("mov.b64 {%0,%1}, %2;" : "=f"(r.x), "=f"(r.y) : "l"(v)); return r;
}

#define CPA16(dst, src) \
    asm volatile("cp.async.cg.shared.global [%0], [%1], 16;" \
                 :: "r"(dst), "l"(src) : "memory")
#define CPA_COMMIT() asm volatile("cp.async.commit_group;" ::: "memory")
#define CPA_WAIT(n)  asm volatile("cp.async.wait_group %0;" :: "n"(n) : "memory")

#define LDSM4(r, addr) \
    asm volatile("ldmatrix.sync.aligned.m8n8.x4.shared.b16 {%0,%1,%2,%3}, [%4];" \
                 : "=r"((r)[0]), "=r"((r)[1]), "=r"((r)[2]), "=r"((r)[3]) \
                 : "r"(addr))

#define MMA_BF16(c, a, b) \
    asm volatile("mma.sync.aligned.m16n8k16.row.col.f32.bf16.bf16.f32 " \
        "{%0,%1,%2,%3}, {%4,%5,%6,%7}, {%8,%9}, {%0,%1,%2,%3};" \
        : "+f"((c)[0]), "+f"((c)[1]), "+f"((c)[2]), "+f"((c)[3]) \
        : "r"((a)[0]), "r"((a)[1]), "r"((a)[2]), "r"((a)[3]), \
          "r"((b)[0]), "r"((b)[1]))

__device__ __forceinline__ uint32_t tile_off(int row, int chunk) {
    return (uint32_t)(row * 64 + ((chunk ^ ((row >> 1) & 3)) << 4));
}

// ---------------------------------------------------------------------------
// HMMA split-bf16 GEMM. 256 threads (8 warps), 3-stage cp.async pipeline.
// EPI=0: partial fp32 store to C + z*M*N (split-K over blockIdx.z).
// EPI=1: bias + relu + bf16 hi/lo split store (G1).
// ---------------------------------------------------------------------------
template<int BM, int BN, int WM, int WN, int EPI>
__global__ __launch_bounds__(256, 1) void gemm_mma(
    const __nv_bfloat16* __restrict__ Ah, const __nv_bfloat16* __restrict__ Al,
    const __nv_bfloat16* __restrict__ Bh, const __nv_bfloat16* __restrict__ Bl,
    const float* __restrict__ bias, float* __restrict__ C,
    __nv_bfloat16* __restrict__ Ch, __nv_bfloat16* __restrict__ Cl,
    int M, int N, int K)
{
    constexpr int BK = 32, STAGES = 3;
    constexpr int THREADS = 256;
    constexpr int A_BYTES = BM * 64;
    constexpr int B_BYTES = BN * 64;
    constexpr int STAGE = 2 * A_BYTES + 2 * B_BYTES;
    constexpr int MT = (BM / WM) / 16;
    constexpr int NT = (BN / WN) / 8;
    constexpr int CHUNKS = (2 * BM + 2 * BN) * 4;
    constexpr int CPT = CHUNKS / THREADS;

    extern __shared__ __align__(128) char dsm[];
    const uint32_t sb = smem_u32(dsm);

    const int tid = threadIdx.x, wid = tid >> 5, lane = tid & 31;
    const int bm = blockIdx.y * BM, bn = blockIdx.x * BN;
    const int wm = wid / WN, wn = wid % WN;
    const int KT = (K / BK) / gridDim.z;          // k-tiles this split owns
    const int kt0 = blockIdx.z * KT;

    auto load_stage = [&](int kt, int s) {
        const uint32_t base = sb + s * STAGE;
        const size_t gk = (size_t)(kt0 + kt) * BK;
        #pragma unroll
        for (int i = 0; i < CPT; i++) {
            int id = tid + i * THREADS;
            int row_all = id >> 2;
            int ck = id & 3;
            const __nv_bfloat16* g;
            uint32_t abase; int row; int rowbase;
            if (row_all < BM)            { g = Ah; abase = 0;                     row = row_all;            rowbase = bm; }
            else if (row_all < 2 * BM)   { g = Al; abase = A_BYTES;               row = row_all - BM;       rowbase = bm; }
            else if (row_all < 2*BM+BN)  { g = Bh; abase = 2 * A_BYTES;           row = row_all - 2 * BM;   rowbase = bn; }
            else                         { g = Bl; abase = 2 * A_BYTES + B_BYTES; row = row_all - 2*BM - BN; rowbase = bn; }
            const __nv_bfloat16* src =
                g + (size_t)(rowbase + row) * K + gk + ck * 8;
            CPA16(base + abase + tile_off(row, ck), src);
        }
        CPA_COMMIT();
    };

    float c[MT][NT][4];
    #pragma unroll
    for (int i = 0; i < MT; i++)
        #pragma unroll
        for (int j = 0; j < NT; j++)
            #pragma unroll
            for (int q = 0; q < 4; q++) c[i][j][q] = 0.f;

    load_stage(0, 0);
    load_stage(1, 1);
    CPA_WAIT(1);
    __syncthreads();

    const int aRow0 = wm * (BM / WM);
    const int bRow0 = wn * (BN / WN);

    for (int kt = 0; kt < KT; kt++) {
        const uint32_t base = sb + (kt % STAGES) * STAGE;
        const uint32_t sAh = base;
        const uint32_t sAl = base + A_BYTES;
        const uint32_t sBh = base + 2 * A_BYTES;
        const uint32_t sBl = base + 2 * A_BYTES + B_BYTES;

        #pragma unroll
        for (int ks = 0; ks < 2; ks++) {
            uint32_t aH[MT][4], aL[MT][4];
            #pragma unroll
            for (int mt = 0; mt < MT; mt++) {
                int row = aRow0 + mt * 16 + (lane & 15);
                int ck = ks * 2 + (lane >> 4);
                uint32_t off = tile_off(row, ck);
                LDSM4(aH[mt], sAh + off);
                LDSM4(aL[mt], sAl + off);
            }
            uint32_t bH[NT][2], bL[NT][2];
            #pragma unroll
            for (int p = 0; p < NT / 2; p++) {
                int row = bRow0 + p * 16 + (lane & 7) + ((lane >> 4) << 3);
                int ck = ks * 2 + ((lane >> 3) & 1);
                uint32_t off = tile_off(row, ck);
                uint32_t r[4];
                LDSM4(r, sBh + off);
                bH[2*p][0] = r[0]; bH[2*p][1] = r[1];
                bH[2*p+1][0] = r[2]; bH[2*p+1][1] = r[3];
                LDSM4(r, sBl + off);
                bL[2*p][0] = r[0]; bL[2*p][1] = r[1];
                bL[2*p+1][0] = r[2]; bL[2*p+1][1] = r[3];
            }
            #pragma unroll
            for (int mt = 0; mt < MT; mt++)
                #pragma unroll
                for (int nt = 0; nt < NT; nt++) {
                    MMA_BF16(c[mt][nt], aH[mt], bH[nt]);
                    MMA_BF16(c[mt][nt], aH[mt], bL[nt]);
                    MMA_BF16(c[mt][nt], aL[mt], bH[nt]);
                }
        }

        if (kt + 2 < KT) {
            load_stage(kt + 2, (kt + 2) % STAGES);
            CPA_WAIT(1);
        } else {
            CPA_WAIT(0);
        }
        __syncthreads();
    }

    // ---- epilogue ----
    float* Cz = C + (size_t)blockIdx.z * M * N;
    #pragma unroll
    for (int mt = 0; mt < MT; mt++) {
        #pragma unroll
        for (int nt = 0; nt < NT; nt++) {
            int row = bm + aRow0 + mt * 16 + (lane >> 2);
            int col = bn + bRow0 + nt * 8 + ((lane & 3) << 1);
            #pragma unroll
            for (int half = 0; half < 2; half++) {
                int r = row + half * 8;
                float v0 = c[mt][nt][half * 2 + 0];
                float v1 = c[mt][nt][half * 2 + 1];
                if (EPI == 0) {
                    Cz[(size_t)r * N + col]     = v0;
                    Cz[(size_t)r * N + col + 1] = v1;
                } else {
                    v0 = fmaxf(v0 + bias[col], 0.f);
                    v1 = fmaxf(v1 + bias[col + 1], 0.f);
                    __nv_bfloat16 h, l;
                    bsplit(v0, h, l);
                    Ch[(size_t)r * N + col] = h; Cl[(size_t)r * N + col] = l;
                    bsplit(v1, h, l);
                    Ch[(size_t)r * N + col + 1] = h; Cl[(size_t)r * N + col + 1] = l;
                }
            }
        }
    }
}

// ---------------------------------------------------------------------------
// K1: logits[bs][h][l] = sum_d x[bs,l,d] * w[h,l,d].  grid (l=128, half=2).
// ---------------------------------------------------------------------------
__global__ __launch_bounds__(256) void logits_kernel(
    const float* __restrict__ x, const float* __restrict__ w,
    float* __restrict__ logits)
{
    __shared__ __align__(16) float w_s[HHn][DDn];
    const int l = blockIdx.x, half = blockIdx.y;
    const int tid = threadIdx.x, warp = tid >> 5, lane = tid & 31;

    #pragma unroll
    for (int i = 0; i < 4; i++) {
        int idx = tid + i * 256;
        int h = idx >> 7, d4 = idx & 127;
        ((float4*)w_s[h])[d4] =
            ((const float4*)(w + ((size_t)(h * LLn + l)) * DDn))[d4];
    }
    __syncthreads();

    const int j  = __brev((unsigned)lane) >> 27;
    const int jb = j >> 3, jh = j & 7;

    #pragma unroll
    for (int q = 0; q < 2; q++) {
        const int bs0 = half * 64 + warp * 8 + q * 4;
        u64 acc[4][HHn];
        #pragma unroll
        for (int b = 0; b < 4; b++)
            #pragma unroll
            for (int h = 0; h < HHn; h++) acc[b][h] = 0ull;

        #pragma unroll
        for (int c = 0; c < 4; c++) {
            const int d4 = c * 32 + lane;
            u64 xp[4][2];
            #pragma unroll
            for (int b = 0; b < 4; b++) {
                double2 xv = ((const double2*)
                    (x + ((size_t)((bs0 + b) * LLn + l)) * DDn))[d4];
                xp[b][0] = __double_as_longlong(xv.x);
                xp[b][1] = __double_as_longlong(xv.y);
            }
            #pragma unroll
            for (int h = 0; h < HHn; h++) {
                double2 wv = ((const double2*)w_s[h])[d4];
                u64 w0 = __double_as_longlong(wv.x);
                u64 w1 = __double_as_longlong(wv.y);
                #pragma unroll
                for (int b = 0; b < 4; b++) {
                    fma2(acc[b][h], xp[b][0], w0);
                    fma2(acc[b][h], xp[b][1], w1);
                }
            }
        }
        float vals[32];
        #pragma unroll
        for (int b = 0; b < 4; b++)
            #pragma unroll
            for (int h = 0; h < HHn; h++) {
                float2 p = upk2(acc[b][h]);
                vals[b * 8 + h] = p.x + p.y;
            }
        #pragma unroll
        for (int s = 0; s < 5; s++) {
            const int n = 32 >> s;
            const int off = 1 << s;
            const bool up = (lane & off) != 0;
            #pragma unroll
            for (int i = 0; i < (n >> 1); i++) {
                float kept = up ? vals[i + (n >> 1)] : vals[i];
                float sent = up ? vals[i] : vals[i + (n >> 1)];
                float r = __shfl_xor_sync(0xffffffffu, sent, off);
                vals[i] = kept + r;
            }
        }
        logits[((size_t)(bs0 + jb) * HHn + jh) * LLn + l] = vals[0];
    }
}

// ---------------------------------------------------------------------------
// K2: fused softmax + ax. grid (bs=128, dhalf=2), block 256.
// ---------------------------------------------------------------------------
__global__ __launch_bounds__(256) void ax_kernel(
    const float* __restrict__ x, const float* __restrict__ logits,
    const int* __restrict__ mask, float* __restrict__ attn_out,
    __nv_bfloat16* __restrict__ axh, __nv_bfloat16* __restrict__ axl)
{
    __shared__ float  a_s[HHn][LLn];
    __shared__ __align__(8) float2 ap[LLn][HHn/2];
    const int bs = blockIdx.x, dh = blockIdx.y;
    const int tid = threadIdx.x, warp = tid >> 5, lane = tid & 31;

    {
        const int h = warp;
        const int row = bs * HHn + h;
        const float invT = 0.0441941738241592f;
        float v[4], mx = -3.4e38f;
        #pragma unroll
        for (int i = 0; i < 4; i++) {
            int l = lane + 32 * i;
            float lg = logits[(size_t)row * LLn + l] * invT;
            if (mask[bs * LLn + l] == 0) lg = -1e9f;
            v[i] = lg; mx = fmaxf(mx, lg);
        }
        #pragma unroll
        for (int off = 16; off; off >>= 1)
            mx = fmaxf(mx, __shfl_xor_sync(0xffffffffu, mx, off));
        float sum = 0.f;
        #pragma unroll
        for (int i = 0; i < 4; i++) { v[i] = __expf(v[i] - mx); sum += v[i]; }
        #pragma unroll
        for (int off = 16; off; off >>= 1)
            sum += __shfl_xor_sync(0xffffffffu, sum, off);
        float inv = 1.f / sum;
        #pragma unroll
        for (int i = 0; i < 4; i++) {
            int l = lane + 32 * i;
            float a = v[i] * inv;
            a_s[h][l] = a;
            if (dh == 0 && attn_out) attn_out[(size_t)row * LLn + l] = a;
        }
    }
    __syncthreads();

    #pragma unroll
    for (int i = tid; i < LLn * 4; i += 256) {
        int l = i >> 2, p = i & 3;
        ap[l][p] = make_float2(a_s[2 * p][l], a_s[2 * p + 1][l]);
    }
    __syncthreads();

    const int d = dh * 256 + tid;
    const float* xp = x + (size_t)bs * LLn * DDn + d;

    u64 acc[4];
    #pragma unroll
    for (int p = 0; p < 4; p++) acc[p] = 0ull;

    #pragma unroll 4
    for (int l = 0; l < LLn; l++) {
        float xv = xp[(size_t)l * DDn];
        u64 xx = pk2(xv, xv);
        #pragma unroll
        for (int p = 0; p < 4; p++) {
            u64 av = __double_as_longlong(*(const double*)&ap[l][p]);
            fma2(acc[p], av, xx);
        }
    }
    #pragma unroll
    for (int p = 0; p < 4; p++) {
        float2 s = upk2(acc[p]);
        size_t o0 = ((size_t)bs * HHn + 2 * p) * DDn + d;
        size_t o1 = ((size_t)bs * HHn + 2 * p + 1) * DDn + d;
        __nv_bfloat16 bh, bl;
        bsplit(s.x, bh, bl); axh[o0] = bh; axl[o0] = bl;
        bsplit(s.y, bh, bl); axh[o1] = bh; axl[o1] = bl;
    }
}

// ---------------------------------------------------------------------------
// Fused split: all three weight tensors fp32 -> (bf16 hi, bf16 lo)
// ---------------------------------------------------------------------------
__global__ __launch_bounds__(256) void split3_kernel(
    const float4* __restrict__ vw, const float4* __restrict__ w1,
    const float4* __restrict__ w2,
    __nv_bfloat16* __restrict__ vwh, __nv_bfloat16* __restrict__ vwl,
    __nv_bfloat16* __restrict__ w1h, __nv_bfloat16* __restrict__ w1l,
    __nv_bfloat16* __restrict__ w2h, __nv_bfloat16* __restrict__ w2l)
{
    constexpr int N0 = DDn * DDn / 4;
    constexpr int N1 = DIn * DDn / 4;
    int i = blockIdx.x * blockDim.x + threadIdx.x;
    const float4* in; __nv_bfloat16 *hi, *lo; int k;
    if (i < N0)            { in = vw; hi = vwh; lo = vwl; k = i; }
    else if (i < N0 + N1)  { in = w1; hi = w1h; lo = w1l; k = i - N0; }
    else                   { in = w2; hi = w2h; lo = w2l; k = i - N0 - N1; }
    float4 v = in[k];
    __nv_bfloat16 h[4], l[4];
    bsplit(v.x, h[0], l[0]); bsplit(v.y, h[1], l[1]);
    bsplit(v.z, h[2], l[2]); bsplit(v.w, h[3], l[3]);
    *(ushort4*)(hi + 4 * (size_t)k) = make_ushort4(
        __bfloat16_as_ushort(h[0]), __bfloat16_as_ushort(h[1]),
        __bfloat16_as_ushort(h[2]), __bfloat16_as_ushort(h[3]));
    *(ushort4*)(lo + 4 * (size_t)k) = make_ushort4(
        __bfloat16_as_ushort(l[0]), __bfloat16_as_ushort(l[1]),
        __bfloat16_as_ushort(l[2]), __bfloat16_as_ushort(l[3]));
}

// ---------------------------------------------------------------------------
// LayerNorm D=512, reducing NPART split-K partials; optional +bias +res.
// ---------------------------------------------------------------------------
__device__ __forceinline__ float block_sum(float v, float* red)
{
    const int lane = threadIdx.x & 31, warp = threadIdx.x >> 5;
    #pragma unroll
    for (int off = 16; off; off >>= 1)
        v += __shfl_xor_sync(0xffffffffu, v, off);
    if (lane == 0) red[warp] = v;
    __syncthreads();
    if (warp == 0) {
        float s = (lane < 8) ? red[lane] : 0.f;
        #pragma unroll
        for (int off = 4; off; off >>= 1)
            s += __shfl_xor_sync(0xffffffffu, s, off);
        if (lane == 0) red[0] = s;
    }
    __syncthreads();
    float rv = red[0];
    __syncthreads();
    return rv;
}

template<int NPART, bool ADDBIAS, bool RES, bool SPLIT>
__global__ __launch_bounds__(256) void ln_kernel(
    const float* __restrict__ parts, const float* __restrict__ bias,
    const float* __restrict__ res,
    const float* __restrict__ g, const float* __restrict__ b,
    float* __restrict__ out,
    __nv_bfloat16* __restrict__ oh, __nv_bfloat16* __restrict__ ol)
{
    __shared__ float red[8];
    const int row = blockIdx.x, tid = threadIdx.x;
    size_t i0 = (size_t)row * DDn + tid, i1 = i0 + 256;

    float v0 = 0.f, v1 = 0.f;
    #pragma unroll
    for (int p = 0; p < NPART; p++) {
        v0 += parts[(size_t)p * NROW * DDn + i0];
        v1 += parts[(size_t)p * NROW * DDn + i1];
    }
    if (ADDBIAS) { v0 += bias[tid]; v1 += bias[tid + 256]; }
    if (RES)     { v0 += res[i0];   v1 += res[i1]; }

    float mu = block_sum(v0 + v1, red) * (1.f / DDn);
    float e0 = v0 - mu, e1 = v1 - mu;
    float var = block_sum(e0 * e0 + e1 * e1, red) * (1.f / DDn);
    float inv = rsqrtf(var + 1e-6f);
    float y0 = e0 * inv * g[tid] + b[tid];
    float y1 = e1 * inv * g[tid + 256] + b[tid + 256];
    if (out) { out[i0] = y0; out[i1] = y1; }
    if (SPLIT) {
        __nv_bfloat16 h, l;
        bsplit(y0, h, l); oh[i0] = h; ol[i0] = l;
        bsplit(y1, h, l); oh[i1] = h; ol[i1] = l;
    }
}

// ---------------------------------------------------------------------------
extern "C" void kernel_launch(void* const* d_in, const int* in_sizes, int n_in,
                              void* d_out, int out_size)
{
    const float* x    = (const float*)d_in[0];
    const int*   mask = (const int*)  d_in[1];
    const float* w    = (const float*)d_in[2];
    const float* v_w  = (const float*)d_in[3];
    const float* ln_g = (const float*)d_in[4];
    const float* ln_b = (const float*)d_in[5];
    const float* w1   = (const float*)d_in[6];
    const float* b1   = (const float*)d_in[7];
    const float* w2   = (const float*)d_in[8];
    const float* b2   = (const float*)d_in[9];
    const float* fg   = (const float*)d_in[10];
    const float* fb   = (const float*)d_in[11];

    float *o, *lg, *pp;
    __nv_bfloat16 *axh, *axl, *oh, *ol, *hh, *hl;
    __nv_bfloat16 *vwh, *vwl, *w1h, *w1l, *w2h, *w2l;
    cudaGetSymbolAddress((void**)&o,   g_o);
    cudaGetSymbolAddress((void**)&lg,  g_logits);
    cudaGetSymbolAddress((void**)&pp,  g_p);
    cudaGetSymbolAddress((void**)&axh, g_axh);
    cudaGetSymbolAddress((void**)&axl, g_axl);
    cudaGetSymbolAddress((void**)&oh,  g_oh);
    cudaGetSymbolAddress((void**)&ol,  g_ol);
    cudaGetSymbolAddress((void**)&hh,  g_hh);
    cudaGetSymbolAddress((void**)&hl,  g_hl);
    cudaGetSymbolAddress((void**)&vwh, g_vwh);
    cudaGetSymbolAddress((void**)&vwl, g_vwl);
    cudaGetSymbolAddress((void**)&w1h, g_w1h);
    cudaGetSymbolAddress((void**)&w1l, g_w1l);
    cudaGetSymbolAddress((void**)&w2h, g_w2h);
    cudaGetSymbolAddress((void**)&w2l, g_w2l);

    float* y_out = (float*)d_out;
    float* attn_out = (out_size >= NROW * DDn + NROW * LLn)
                        ? (y_out + NROW * DDn) : nullptr;

    constexpr int SM6464  = 3 * (2 * 64 * 64 + 2 * 64 * 64);    // 49152
    constexpr int SM64128 = 3 * (2 * 64 * 64 + 2 * 128 * 64);   // 73728
    cudaFuncSetAttribute(gemm_mma<64, 64, 2, 4, 0>,
                         cudaFuncAttributeMaxDynamicSharedMemorySize, SM6464);
    cudaFuncSetAttribute(gemm_mma<64, 128, 2, 4, 1>,
                         cudaFuncAttributeMaxDynamicSharedMemorySize, SM64128);

    // all weight splits in one launch
    constexpr int NSPLIT = (DDn*DDn + DIn*DDn + DDn*DIn) / 4;
    split3_kernel<<<NSPLIT/256, 256>>>(
        (const float4*)v_w, (const float4*)w1, (const float4*)w2,
        vwh, vwl, w1h, w1l, w2h, w2l);

    // attention: logits -> fused softmax + attn@x
    logits_kernel<<<dim3(LLn, 2), 256>>>(x, w, lg);
    ax_kernel<<<dim3(NBS, 2), 256>>>(x, lg, mask, attn_out, axh, axl);

    // G0: ax @ v_w^T, split-K2 -> partials p0,p1   (1024 x 512 x 512)
    gemm_mma<64, 64, 2, 4, 0>
        <<<dim3(DDn/64, NROW/64, 2), 256, SM6464>>>(
        axh, axl, vwh, vwl, nullptr, pp, nullptr, nullptr,
        NROW, DDn, DDn);

    // o = LN(p0+p1) (+ split)
    ln_kernel<2, false, false, true><<<NROW, 256>>>(
        pp, nullptr, nullptr, ln_g, ln_b, o, oh, ol);

    // G1: h = relu(o @ w1^T + b1), split bf16 out  (1024 x 2048 x 512)
    gemm_mma<64, 128, 2, 4, 1>
        <<<dim3(DIn/128, NROW/64, 1), 256, SM64128>>>(
        oh, ol, w1h, w1l, b1, nullptr, hh, hl,
        NROW, DIn, DDn);

    // G2: h @ w2^T, split-K4 -> partials p0..p3    (1024 x 512 x 2048)
    gemm_mma<64, 64, 2, 4, 0>
        <<<dim3(DDn/64, NROW/64, 4), 256, SM6464>>>(
        hh, hl, w2h, w2l, nullptr, pp, nullptr, nullptr,
        NROW, DDn, DIn);

    // y = LN(p0+p1+p2+p3 + b2 + o)
    ln_kernel<4, true, true, false><<<NROW, 256>>>(
        pp, b2, o, fg, fb, y_out, nullptr, nullptr);
}